// round 12
// baseline (speedup 1.0000x reference)
#include <cuda_runtime.h>
#include <cuda_bf16.h>
#include <math_constants.h>
#include <cstdint>

#define NROWS 8192
#define DDIM  128
#define NCLS  10
#define GAPV  0.4f
#define NTILE 64
#define SUB   16384          // one 128-row x 64-k bf16 swizzled sub-image
#define NUNITS 2080          // 64*65/2 upper-triangular tiles
#define NCTA  148
#define STAGE 65536          // A_H,A_L,B_H,B_L sub-images (4 x 16KB)
#define NSTG  3

// -------- device scratch (no allocation allowed) ---------------------------
__device__ __align__(128) unsigned char g_H_img[NROWS * 256];
__device__ __align__(128) unsigned char g_L_img[NROWS * 256];
__device__ float    g_sq[NROWS];
__device__ unsigned g_ap[NROWS];
__device__ unsigned g_an[NROWS];
__device__ int      g_cls[NROWS];
__device__ float    g_part[64];

// -------- helpers ----------------------------------------------------------
__device__ __forceinline__ unsigned smem_u32(const void* p) {
    unsigned a;
    asm("{ .reg .u64 t; cvta.to.shared.u64 t, %1; cvt.u32.u64 %0, t; }" : "=r"(a) : "l"(p));
    return a;
}
__device__ __forceinline__ void mbar_init(unsigned a, unsigned cnt) {
    asm volatile("mbarrier.init.shared.b64 [%0], %1;" :: "r"(a), "r"(cnt) : "memory");
}
__device__ __forceinline__ void mbar_arrive(unsigned a) {
    asm volatile("mbarrier.arrive.shared.b64 _, [%0];" :: "r"(a) : "memory");
}
__device__ __forceinline__ void mbar_expect_tx(unsigned a, unsigned bytes) {
    asm volatile("mbarrier.arrive.expect_tx.shared.b64 _, [%0], %1;" :: "r"(a), "r"(bytes) : "memory");
}
__device__ __forceinline__ void mbar_wait(unsigned a, unsigned ph) {
    asm volatile(
        "{\n\t.reg .pred P;\n\t"
        "W_%=:\n\t"
        "mbarrier.try_wait.parity.acquire.cta.shared::cta.b64 P, [%0], %1, 0x989680;\n\t"
        "@P bra.uni D_%=;\n\t"
        "bra.uni W_%=;\n\t"
        "D_%=:\n\t}"
        :: "r"(a), "r"(ph) : "memory");
}
__device__ __forceinline__ void bulk_g2s(unsigned dst, const void* src, unsigned bytes, unsigned mbar) {
    asm volatile(
        "cp.async.bulk.shared::cluster.global.mbarrier::complete_tx::bytes [%0], [%1], %2, [%3];"
        :: "r"(dst), "l"(src), "r"(bytes), "r"(mbar) : "memory");
}
__device__ __forceinline__ void ldsm4(unsigned* r, unsigned addr) {
    asm volatile("ldmatrix.sync.aligned.m8n8.x4.shared.b16 {%0,%1,%2,%3}, [%4];"
        : "=r"(r[0]), "=r"(r[1]), "=r"(r[2]), "=r"(r[3]) : "r"(addr));
}
__device__ __forceinline__ void mma16816(float* c, const unsigned* a, unsigned b0, unsigned b1) {
    asm volatile(
        "mma.sync.aligned.m16n8k16.row.col.f32.bf16.bf16.f32 "
        "{%0,%1,%2,%3}, {%4,%5,%6,%7}, {%8,%9}, {%0,%1,%2,%3};"
        : "+f"(c[0]), "+f"(c[1]), "+f"(c[2]), "+f"(c[3])
        : "r"(a[0]), "r"(a[1]), "r"(a[2]), "r"(a[3]), "r"(b0), "r"(b1));
}
__device__ __forceinline__ unsigned sub_off(int r, int kbyte) {
    return (unsigned)r * 128u + ((unsigned)kbyte ^ (((unsigned)r & 7u) << 4));
}

// ---------------------------------------------------------------------------
// Kernel 0: normalize targets (int32 vs int64-low-word autodetect).
// ---------------------------------------------------------------------------
__global__ void classes_kernel(const int* __restrict__ tgt32) {
    __shared__ int s_stride;
    int tid = threadIdx.x;
    if (tid == 0) {
        int any = 0;
        #pragma unroll
        for (int i = 1; i < 128; i += 2) any |= tgt32[i];
        s_stride = (any == 0) ? 2 : 1;
    }
    __syncthreads();
    int stride = s_stride;
    for (int i = blockIdx.x * 1024 + tid; i < NROWS; i += gridDim.x * 1024)
        g_cls[i] = tgt32[i * stride];
}

// ---------------------------------------------------------------------------
// Kernel 1: split X -> bf16 H/L khalf-split swizzled images; row norms; reset.
// ---------------------------------------------------------------------------
__global__ void convert_kernel(const float* __restrict__ X) {
    int wid = threadIdx.x >> 5, lane = threadIdx.x & 31;
    int row = blockIdx.x * 8 + wid;
    int k4  = lane * 4;

    float4 v = *reinterpret_cast<const float4*>(X + (size_t)row * DDIM + k4);
    float s = v.x * v.x + v.y * v.y + v.z * v.z + v.w * v.w;
    #pragma unroll
    for (int m = 16; m > 0; m >>= 1) s += __shfl_xor_sync(0xffffffffu, s, m);
    if (lane == 0) {
        g_sq[row] = s;
        g_ap[row] = 0u;
        g_an[row] = 0x7f800000u;
    }

    __nv_bfloat16 h0 = __float2bfloat16(v.x), h1 = __float2bfloat16(v.y);
    __nv_bfloat16 h2 = __float2bfloat16(v.z), h3 = __float2bfloat16(v.w);
    __nv_bfloat16 l0 = __float2bfloat16(v.x - __bfloat162float(h0));
    __nv_bfloat16 l1 = __float2bfloat16(v.y - __bfloat162float(h1));
    __nv_bfloat16 l2 = __float2bfloat16(v.z - __bfloat162float(h2));
    __nv_bfloat16 l3 = __float2bfloat16(v.w - __bfloat162float(h3));

    uint2 hp, lp;
    hp.x = ((unsigned)__bfloat16_as_ushort(h1) << 16) | __bfloat16_as_ushort(h0);
    hp.y = ((unsigned)__bfloat16_as_ushort(h3) << 16) | __bfloat16_as_ushort(h2);
    lp.x = ((unsigned)__bfloat16_as_ushort(l1) << 16) | __bfloat16_as_ushort(l0);
    lp.y = ((unsigned)__bfloat16_as_ushort(l3) << 16) | __bfloat16_as_ushort(l2);

    int tile = row >> 7, r = row & 127;
    int kh = (k4 >= 64) ? 1 : 0;
    int kb = (k4 & 63) * 2;
    size_t base = ((size_t)tile * 2 + kh) * SUB + sub_off(r, kb);
    *reinterpret_cast<uint2*>(g_H_img + base) = hp;
    *reinterpret_cast<uint2*>(g_L_img + base) = lp;
}

// profiling slot shifter (no-op)
__global__ void probe_kernel() {}

// ---------------------------------------------------------------------------
// Kernel 2: persistent triangle HMMA Gram + smem-combined dual epilogue.
// 148 CTAs x 512 thr (16 warps, 4x4 grid, 32x32/warp). 3-stage 64KB ring.
// Terms: HH + HL + LH.
// ---------------------------------------------------------------------------
__global__ __launch_bounds__(512) void gram_kernel() {
    extern __shared__ __align__(128) unsigned char dsm[];
    __shared__ __align__(8) unsigned long long s_full[NSTG], s_empty[NSTG];
    __shared__ float s_sqr[128], s_sqc[128];
    __shared__ int   s_clsr[128], s_clsc[128];
    __shared__ unsigned s_apr[128], s_anr[128], s_apc[128], s_anc[128];

    const int tid = threadIdx.x, lane = tid & 31, w = tid >> 5;
    const int warp_m = w & 3, warp_n = w >> 2;
    const int bid = blockIdx.x;
    const unsigned sbase = smem_u32(dsm);

    if (tid == 0) {
        #pragma unroll
        for (int s = 0; s < NSTG; s++) {
            mbar_init(smem_u32(&s_full[s]), 1);
            mbar_init(smem_u32(&s_empty[s]), 16);
        }
    }
    __syncthreads();

    unsigned mbf[NSTG], mbe[NSTG];
    #pragma unroll
    for (int s = 0; s < NSTG; s++) { mbf[s] = smem_u32(&s_full[s]); mbe[s] = smem_u32(&s_empty[s]); }
    unsigned phf[NSTG] = {0, 0, 0}, phe[NSTG] = {0, 0, 0};

    const int nu = 1 + (NUNITS - 1 - bid) / NCTA;
    const int total_g = nu * 2;

    auto issue = [&](int g2) {
        int ord = g2 >> 1, kh = g2 & 1;
        int u = bid + ord * NCTA;
        int ti2 = 0, rem = u;
        while (rem >= NTILE - ti2) { rem -= NTILE - ti2; ti2++; }
        int tj2 = ti2 + rem;
        int st = g2 % NSTG;
        unsigned dst = sbase + (unsigned)st * STAGE;
        mbar_expect_tx(mbf[st], STAGE);
        bulk_g2s(dst,          g_H_img + ((size_t)ti2 * 2 + kh) * SUB, SUB, mbf[st]);
        bulk_g2s(dst + 16384u, g_L_img + ((size_t)ti2 * 2 + kh) * SUB, SUB, mbf[st]);
        bulk_g2s(dst + 32768u, g_H_img + ((size_t)tj2 * 2 + kh) * SUB, SUB, mbf[st]);
        bulk_g2s(dst + 49152u, g_L_img + ((size_t)tj2 * 2 + kh) * SUB, SUB, mbf[st]);
    };

    if (tid == 0) {
        if (total_g > 0) issue(0);
        if (total_g > 1) issue(1);
        if (total_g > 2) issue(2);
    }

    // per-lane ldmatrix address components
    const int aR = lane & 15;
    const int aK = (lane >> 4) * 16;
    const int bN = (lane & 7) + ((lane >> 4) << 3);
    const int bK = ((lane >> 3) & 1) * 16;
    unsigned aoff[2], asw[2];
    #pragma unroll
    for (int mi = 0; mi < 2; mi++) {
        int r = warp_m * 32 + mi * 16 + aR;
        aoff[mi] = (unsigned)r * 128u;
        asw[mi]  = ((unsigned)r & 7u) << 4;
    }
    unsigned boff[2], bsw[2];
    #pragma unroll
    for (int p = 0; p < 2; p++) {
        int r = warp_n * 32 + p * 16 + bN;
        boff[p] = (unsigned)r * 128u;
        bsw[p]  = ((unsigned)r & 7u) << 4;
    }
    const int qr = lane >> 2;
    const int qc = (lane & 3) * 2;

    float acc[2][4][4];
    int ti = 0, tj = 0;

    for (int g = 0; g < total_g; ++g) {
        const int st = g % NSTG;
        const int kh = g & 1;

        if (kh == 0) {
            int u = bid + (g >> 1) * NCTA;
            int t0 = 0, rem = u;
            while (rem >= NTILE - t0) { rem -= NTILE - t0; t0++; }
            ti = t0; tj = t0 + rem;
            __syncthreads();     // prior tile's flush done
            if (tid < 128) {
                int gi = ti * 128 + tid;
                s_sqr[tid] = g_sq[gi]; s_clsr[tid] = g_cls[gi];
            } else if (tid < 256) {
                int tl = tid - 128, gi = tj * 128 + tl;
                s_sqc[tl] = g_sq[gi]; s_clsc[tl] = g_cls[gi];
            } else if (tid < 384) {
                int tl = tid - 256;
                s_apr[tl] = 0u; s_anr[tl] = 0x7f800000u;
            } else {
                int tl = tid - 384;
                s_apc[tl] = 0u; s_anc[tl] = 0x7f800000u;
            }
            __syncthreads();     // stats + reduction arrays ready
            #pragma unroll
            for (int mi = 0; mi < 2; mi++)
                #pragma unroll
                for (int ni = 0; ni < 4; ni++)
                    #pragma unroll
                    for (int x = 0; x < 4; x++) acc[mi][ni][x] = 0.0f;
        }

        mbar_wait(mbf[st], phf[st]); phf[st] ^= 1;

        const unsigned AH = sbase + (unsigned)st * STAGE;
        const unsigned AL = AH + 16384u, BH = AH + 32768u, BL = AH + 49152u;

        #pragma unroll
        for (int ks = 0; ks < 4; ++ks) {
            const unsigned kbA = (unsigned)(ks * 32 + aK);
            const unsigned kbB = (unsigned)(ks * 32 + bK);
            unsigned ah[2][4], al[2][4], bh[2][4], bl[2][4];
            #pragma unroll
            for (int mi = 0; mi < 2; mi++) {
                ldsm4(ah[mi], AH + aoff[mi] + (kbA ^ asw[mi]));
                ldsm4(al[mi], AL + aoff[mi] + (kbA ^ asw[mi]));
            }
            #pragma unroll
            for (int p = 0; p < 2; p++) {
                ldsm4(bh[p], BH + boff[p] + (kbB ^ bsw[p]));
                ldsm4(bl[p], BL + boff[p] + (kbB ^ bsw[p]));
            }
            #pragma unroll
            for (int mi = 0; mi < 2; mi++)
                #pragma unroll
                for (int ni = 0; ni < 4; ni++) {
                    const int p = ni >> 1, s2 = (ni & 1) * 2;
                    mma16816(acc[mi][ni], ah[mi], bh[p][s2], bh[p][s2 + 1]); // H.H
                    mma16816(acc[mi][ni], ah[mi], bl[p][s2], bl[p][s2 + 1]); // H.L
                    mma16816(acc[mi][ni], al[mi], bh[p][s2], bh[p][s2 + 1]); // L.H
                }
        }
        if (lane == 0) mbar_arrive(mbe[st]);

        if (tid == 0 && g + 3 < total_g) {
            int st3 = (g + 3) % NSTG;
            mbar_wait(mbe[st3], phe[st3]); phe[st3] ^= 1;
            issue(g + 3);
        }

        if (kh == 1) {
            // ---- dual-sided epilogue into smem reduction arrays ----
            const int cb = warp_n * 32;
            float cmx[4][2], cmn[4][2];
            #pragma unroll
            for (int ni = 0; ni < 4; ni++) {
                cmx[ni][0] = cmx[ni][1] = -CUDART_INF_F;
                cmn[ni][0] = cmn[ni][1] =  CUDART_INF_F;
            }
            #pragma unroll
            for (int mi = 0; mi < 2; mi++) {
                const int rl = warp_m * 32 + mi * 16 + qr;
                const int rh = rl + 8;
                const float sql = s_sqr[rl], sqh = s_sqr[rh];
                const int crl = s_clsr[rl], crh = s_clsr[rh];
                float apl = -CUDART_INF_F, anl = CUDART_INF_F;
                float aph = -CUDART_INF_F, anh = CUDART_INF_F;
                #pragma unroll
                for (int ni = 0; ni < 4; ni++) {
                    const int c0 = cb + ni * 8 + qc, c1 = c0 + 1;
                    const float sc0 = s_sqc[c0], sc1 = s_sqc[c1];
                    const int k0 = s_clsc[c0], k1 = s_clsc[c1];
                    const float d00 = acc[mi][ni][0], d01 = acc[mi][ni][1];
                    const float d10 = acc[mi][ni][2], d11 = acc[mi][ni][3];
                    const bool m0l = (k0 == crl), m1l = (k1 == crl);
                    const bool m0h = (k0 == crh), m1h = (k1 == crh);
                    const float r00 = fmaf(-2.0f, d00, sc0), r01 = fmaf(-2.0f, d01, sc1);
                    const float r10 = fmaf(-2.0f, d10, sc0), r11 = fmaf(-2.0f, d11, sc1);
                    apl = fmaxf(apl, m0l ? r00 : -CUDART_INF_F);
                    apl = fmaxf(apl, m1l ? r01 : -CUDART_INF_F);
                    anl = fminf(anl, m0l ? CUDART_INF_F : r00);
                    anl = fminf(anl, m1l ? CUDART_INF_F : r01);
                    aph = fmaxf(aph, m0h ? r10 : -CUDART_INF_F);
                    aph = fmaxf(aph, m1h ? r11 : -CUDART_INF_F);
                    anh = fminf(anh, m0h ? CUDART_INF_F : r10);
                    anh = fminf(anh, m1h ? CUDART_INF_F : r11);
                    const float q00 = fmaf(-2.0f, d00, sql), q01 = fmaf(-2.0f, d01, sql);
                    const float q10 = fmaf(-2.0f, d10, sqh), q11 = fmaf(-2.0f, d11, sqh);
                    cmx[ni][0] = fmaxf(cmx[ni][0], m0l ? q00 : -CUDART_INF_F);
                    cmx[ni][0] = fmaxf(cmx[ni][0], m0h ? q10 : -CUDART_INF_F);
                    cmx[ni][1] = fmaxf(cmx[ni][1], m1l ? q01 : -CUDART_INF_F);
                    cmx[ni][1] = fmaxf(cmx[ni][1], m1h ? q11 : -CUDART_INF_F);
                    cmn[ni][0] = fminf(cmn[ni][0], m0l ? CUDART_INF_F : q00);
                    cmn[ni][0] = fminf(cmn[ni][0], m0h ? CUDART_INF_F : q10);
                    cmn[ni][1] = fminf(cmn[ni][1], m1l ? CUDART_INF_F : q01);
                    cmn[ni][1] = fminf(cmn[ni][1], m1h ? CUDART_INF_F : q11);
                }
                #pragma unroll
                for (int m = 1; m < 4; m <<= 1) {
                    apl = fmaxf(apl, __shfl_xor_sync(0xffffffffu, apl, m));
                    anl = fminf(anl, __shfl_xor_sync(0xffffffffu, anl, m));
                    aph = fmaxf(aph, __shfl_xor_sync(0xffffffffu, aph, m));
                    anh = fminf(anh, __shfl_xor_sync(0xffffffffu, anh, m));
                }
                if ((lane & 3) == 0) {
                    atomicMax(&s_apr[rl], __float_as_uint(fmaxf(sql + apl, 1e-12f)));
                    atomicMin(&s_anr[rl], __float_as_uint(fmaxf(sql + anl, 1e-12f)));
                    atomicMax(&s_apr[rh], __float_as_uint(fmaxf(sqh + aph, 1e-12f)));
                    atomicMin(&s_anr[rh], __float_as_uint(fmaxf(sqh + anh, 1e-12f)));
                }
            }
            #pragma unroll
            for (int ni = 0; ni < 4; ni++)
                #pragma unroll
                for (int j = 0; j < 2; j++)
                    #pragma unroll
                    for (int m = 4; m < 32; m <<= 1) {
                        cmx[ni][j] = fmaxf(cmx[ni][j], __shfl_xor_sync(0xffffffffu, cmx[ni][j], m));
                        cmn[ni][j] = fminf(cmn[ni][j], __shfl_xor_sync(0xffffffffu, cmn[ni][j], m));
                    }
            if (qr == 0) {   // lanes 0..3
                #pragma unroll
                for (int ni = 0; ni < 4; ni++)
                    #pragma unroll
                    for (int j = 0; j < 2; j++) {
                        const int c = cb + ni * 8 + (lane & 3) * 2 + j;
                        const float sc = s_sqc[c];
                        atomicMax(&s_apc[c], __float_as_uint(fmaxf(cmx[ni][j] + sc, 1e-12f)));
                        atomicMin(&s_anc[c], __float_as_uint(fmaxf(cmn[ni][j] + sc, 1e-12f)));
                    }
            }
            __syncthreads();   // all smem reductions done
            if (tid < 128) {
                const int gr = ti * 128 + tid, gc = tj * 128 + tid;
                atomicMax(&g_ap[gr], s_apr[tid]);
                atomicMin(&g_an[gr], s_anr[tid]);
                atomicMax(&g_ap[gc], s_apc[tid]);
                atomicMin(&g_an[gc], s_anc[tid]);
            }
        }
    }
}

// ---------------------------------------------------------------------------
// Kernel 3: per-row confusion + partial sums. 32 blocks x 256.
// ---------------------------------------------------------------------------
__global__ void confuse_kernel(const float* __restrict__ pred) {
    __shared__ float s_s[8], s_c[8];
    int i = blockIdx.x * 256 + threadIdx.x;

    const float* pr = pred + (size_t)i * NCLS;
    float l[NCLS];
    float mx = -CUDART_INF_F;
    #pragma unroll
    for (int c = 0; c < NCLS; c++) { l[c] = pr[c]; mx = fmaxf(mx, l[c]); }
    float s = 0.0f;
    #pragma unroll
    for (int c = 0; c < NCLS; c++) { l[c] = __expf(l[c] - mx); s += l[c]; }
    float inv = 1.0f / s;
    float v1 = -1.0f, v2 = -1.0f;
    int i1 = 0;
    #pragma unroll
    for (int c = 0; c < NCLS; c++) {
        float p = l[c] * inv;
        if (p > v1) { v2 = v1; v1 = p; i1 = c; }
        else if (p > v2) { v2 = p; }
    }
    bool confuse = ((v1 - v2) <= GAPV) || (i1 != g_cls[i]);

    float ap = sqrtf(__uint_as_float(g_ap[i]));
    float an = sqrtf(__uint_as_float(g_an[i]));
    float per = fmaxf(ap - an, 0.0f);
    float sum = confuse ? per : 0.0f;
    float cnt = confuse ? 1.0f : 0.0f;

    #pragma unroll
    for (int m = 16; m > 0; m >>= 1) {
        sum += __shfl_xor_sync(0xffffffffu, sum, m);
        cnt += __shfl_xor_sync(0xffffffffu, cnt, m);
    }
    int wid = threadIdx.x >> 5, lane = threadIdx.x & 31;
    if (lane == 0) { s_s[wid] = sum; s_c[wid] = cnt; }
    __syncthreads();
    if (threadIdx.x == 0) {
        float ts = 0.0f, tc = 0.0f;
        #pragma unroll
        for (int w2 = 0; w2 < 8; w2++) { ts += s_s[w2]; tc += s_c[w2]; }
        g_part[blockIdx.x * 2]     = ts;
        g_part[blockIdx.x * 2 + 1] = tc;
    }
}

__global__ void final_kernel(float* __restrict__ out) {
    float s = 0.0f, c = 0.0f;
    #pragma unroll
    for (int b = 0; b < 32; b++) { s += g_part[b * 2]; c += g_part[b * 2 + 1]; }
    out[0] = (c > 0.0f) ? (s / c) : 0.0f;
}

// ---------------------------------------------------------------------------
extern "C" void kernel_launch(void* const* d_in, const int* in_sizes, int n_in,
                              void* d_out, int out_size) {
    const float* X    = (const float*)d_in[0];
    const float* pred = (const float*)d_in[1];
    const int*   tgt  = (const int*)d_in[2];
    float* out = (float*)d_out;

    static int smem_set = 0;
    const int SMEM_DYN = NSTG * STAGE;   // 196608
    if (!smem_set) {
        cudaFuncSetAttribute(gram_kernel,
                             cudaFuncAttributeMaxDynamicSharedMemorySize, SMEM_DYN);
        smem_set = 1;
    }

    classes_kernel<<<8, 1024>>>(tgt);
    convert_kernel<<<NROWS / 8, 256>>>(X);
    probe_kernel<<<1, 32>>>();          // shifts ncu capture slot onto gram_kernel
    gram_kernel<<<NCTA, 512, SMEM_DYN>>>();
    confuse_kernel<<<32, 256>>>(pred);
    final_kernel<<<1, 1>>>(out);
}

// round 15
// speedup vs baseline: 1.1968x; 1.1968x over previous
#include <cuda_runtime.h>
#include <cuda_bf16.h>
#include <math_constants.h>
#include <cstdint>

#define NROWS 8192
#define DDIM  128
#define NCLS  10
#define GAPV  0.4f
#define NTILE 64
#define SUB   16384          // one 128-row x 64-k bf16 swizzled sub-image
#define NUNITS 1056          // sum_{p=0..31} (64 - 2p) row-pair x col-tile units
#define NCTA  148
#define STAGE 98304          // A0H,A0L,A1H,A1L,BH,BL (6 x 16KB)
#define NSTG  2

// -------- device scratch (no allocation allowed) ---------------------------
__device__ __align__(128) unsigned char g_H_img[NROWS * 256];
__device__ __align__(128) unsigned char g_L_img[NROWS * 256];
__device__ float    g_sq[NROWS];
__device__ unsigned g_ap[NROWS];
__device__ unsigned g_an[NROWS];
__device__ int      g_cls[NROWS];
__device__ float    g_part[64];

// -------- helpers ----------------------------------------------------------
__device__ __forceinline__ unsigned smem_u32(const void* p) {
    unsigned a;
    asm("{ .reg .u64 t; cvta.to.shared.u64 t, %1; cvt.u32.u64 %0, t; }" : "=r"(a) : "l"(p));
    return a;
}
__device__ __forceinline__ void mbar_init(unsigned a, unsigned cnt) {
    asm volatile("mbarrier.init.shared.b64 [%0], %1;" :: "r"(a), "r"(cnt) : "memory");
}
__device__ __forceinline__ void mbar_arrive(unsigned a) {
    asm volatile("mbarrier.arrive.shared.b64 _, [%0];" :: "r"(a) : "memory");
}
__device__ __forceinline__ void mbar_expect_tx(unsigned a, unsigned bytes) {
    asm volatile("mbarrier.arrive.expect_tx.shared.b64 _, [%0], %1;" :: "r"(a), "r"(bytes) : "memory");
}
__device__ __forceinline__ void mbar_wait(unsigned a, unsigned ph) {
    asm volatile(
        "{\n\t.reg .pred P;\n\t"
        "W_%=:\n\t"
        "mbarrier.try_wait.parity.acquire.cta.shared::cta.b64 P, [%0], %1, 0x989680;\n\t"
        "@P bra.uni D_%=;\n\t"
        "bra.uni W_%=;\n\t"
        "D_%=:\n\t}"
        :: "r"(a), "r"(ph) : "memory");
}
__device__ __forceinline__ void bulk_g2s(unsigned dst, const void* src, unsigned bytes, unsigned mbar) {
    asm volatile(
        "cp.async.bulk.shared::cluster.global.mbarrier::complete_tx::bytes [%0], [%1], %2, [%3];"
        :: "r"(dst), "l"(src), "r"(bytes), "r"(mbar) : "memory");
}
__device__ __forceinline__ void ldsm4(unsigned* r, unsigned addr) {
    asm volatile("ldmatrix.sync.aligned.m8n8.x4.shared.b16 {%0,%1,%2,%3}, [%4];"
        : "=r"(r[0]), "=r"(r[1]), "=r"(r[2]), "=r"(r[3]) : "r"(addr));
}
__device__ __forceinline__ void mma16816(float* c, const unsigned* a, unsigned b0, unsigned b1) {
    asm volatile(
        "mma.sync.aligned.m16n8k16.row.col.f32.bf16.bf16.f32 "
        "{%0,%1,%2,%3}, {%4,%5,%6,%7}, {%8,%9}, {%0,%1,%2,%3};"
        : "+f"(c[0]), "+f"(c[1]), "+f"(c[2]), "+f"(c[3])
        : "r"(a[0]), "r"(a[1]), "r"(a[2]), "r"(a[3]), "r"(b0), "r"(b1));
}
__device__ __forceinline__ unsigned sub_off(int r, int kbyte) {
    return (unsigned)r * 128u + ((unsigned)kbyte ^ (((unsigned)r & 7u) << 4));
}

// ---------------------------------------------------------------------------
// Kernel 0: normalize targets (int32 vs int64-low-word autodetect).
// ---------------------------------------------------------------------------
__global__ void classes_kernel(const int* __restrict__ tgt32) {
    __shared__ int s_stride;
    int tid = threadIdx.x;
    if (tid == 0) {
        int any = 0;
        #pragma unroll
        for (int i = 1; i < 128; i += 2) any |= tgt32[i];
        s_stride = (any == 0) ? 2 : 1;
    }
    __syncthreads();
    int stride = s_stride;
    for (int i = blockIdx.x * 1024 + tid; i < NROWS; i += gridDim.x * 1024)
        g_cls[i] = tgt32[i * stride];
}

// ---------------------------------------------------------------------------
// Kernel 1: split X -> bf16 H/L khalf-split swizzled images; row norms; reset.
// ---------------------------------------------------------------------------
__global__ void convert_kernel(const float* __restrict__ X) {
    int wid = threadIdx.x >> 5, lane = threadIdx.x & 31;
    int row = blockIdx.x * 8 + wid;
    int k4  = lane * 4;

    float4 v = *reinterpret_cast<const float4*>(X + (size_t)row * DDIM + k4);
    float s = v.x * v.x + v.y * v.y + v.z * v.z + v.w * v.w;
    #pragma unroll
    for (int m = 16; m > 0; m >>= 1) s += __shfl_xor_sync(0xffffffffu, s, m);
    if (lane == 0) {
        g_sq[row] = s;
        g_ap[row] = 0u;
        g_an[row] = 0x7f800000u;
    }

    __nv_bfloat16 h0 = __float2bfloat16(v.x), h1 = __float2bfloat16(v.y);
    __nv_bfloat16 h2 = __float2bfloat16(v.z), h3 = __float2bfloat16(v.w);
    __nv_bfloat16 l0 = __float2bfloat16(v.x - __bfloat162float(h0));
    __nv_bfloat16 l1 = __float2bfloat16(v.y - __bfloat162float(h1));
    __nv_bfloat16 l2 = __float2bfloat16(v.z - __bfloat162float(h2));
    __nv_bfloat16 l3 = __float2bfloat16(v.w - __bfloat162float(h3));

    uint2 hp, lp;
    hp.x = ((unsigned)__bfloat16_as_ushort(h1) << 16) | __bfloat16_as_ushort(h0);
    hp.y = ((unsigned)__bfloat16_as_ushort(h3) << 16) | __bfloat16_as_ushort(h2);
    lp.x = ((unsigned)__bfloat16_as_ushort(l1) << 16) | __bfloat16_as_ushort(l0);
    lp.y = ((unsigned)__bfloat16_as_ushort(l3) << 16) | __bfloat16_as_ushort(l2);

    int tile = row >> 7, r = row & 127;
    int kh = (k4 >= 64) ? 1 : 0;
    int kb = (k4 & 63) * 2;
    size_t base = ((size_t)tile * 2 + kh) * SUB + sub_off(r, kb);
    *reinterpret_cast<uint2*>(g_H_img + base) = hp;
    *reinterpret_cast<uint2*>(g_L_img + base) = lp;
}

// profiling slot shifter (no-op)
__global__ void probe_kernel() {}

// ---------------------------------------------------------------------------
// Kernel 2: persistent triangle HMMA Gram, 256x128 units, 8 warps (64x64 each),
// 2-stage 96KB ring, smem-combined dual epilogue. Terms: HH + HL + LH.
// ---------------------------------------------------------------------------
__global__ __launch_bounds__(256) void gram_kernel() {
    extern __shared__ __align__(128) unsigned char dsm[];
    __shared__ __align__(8) unsigned long long s_full[NSTG], s_empty[NSTG];
    __shared__ float s_sqr[256], s_sqc[128];
    __shared__ int   s_clsr[256], s_clsc[128];
    __shared__ unsigned s_apr[256], s_anr[256], s_apc[128], s_anc[128];

    const int tid = threadIdx.x, lane = tid & 31, w = tid >> 5;
    const int warp_m = w & 3, warp_n = w >> 2;   // 4 x 2 grid, 64x64 per warp
    const int bid = blockIdx.x;
    const unsigned sbase = smem_u32(dsm);

    if (tid == 0) {
        #pragma unroll
        for (int s = 0; s < NSTG; s++) {
            mbar_init(smem_u32(&s_full[s]), 1);
            mbar_init(smem_u32(&s_empty[s]), 8);
        }
    }
    __syncthreads();

    unsigned mbf[NSTG], mbe[NSTG];
    #pragma unroll
    for (int s = 0; s < NSTG; s++) { mbf[s] = smem_u32(&s_full[s]); mbe[s] = smem_u32(&s_empty[s]); }
    unsigned phf[NSTG] = {0, 0}, phe[NSTG] = {0, 0};

    const int nu = 1 + (NUNITS - 1 - bid) / NCTA;
    const int total_g = nu * 2;

    auto issue = [&](int g2) {
        int ord = g2 >> 1, khh = g2 & 1;
        int u = bid + ord * NCTA;
        int p = 0, rem = u;
        while (rem >= NTILE - 2 * p) { rem -= NTILE - 2 * p; p++; }
        int j = 2 * p + rem;
        int st2 = g2 & 1;
        unsigned dst = sbase + (unsigned)st2 * STAGE;
        mbar_expect_tx(mbf[st2], STAGE);
        bulk_g2s(dst,           g_H_img + ((size_t)(2 * p)     * 2 + khh) * SUB, SUB, mbf[st2]);
        bulk_g2s(dst + 16384u,  g_L_img + ((size_t)(2 * p)     * 2 + khh) * SUB, SUB, mbf[st2]);
        bulk_g2s(dst + 32768u,  g_H_img + ((size_t)(2 * p + 1) * 2 + khh) * SUB, SUB, mbf[st2]);
        bulk_g2s(dst + 49152u,  g_L_img + ((size_t)(2 * p + 1) * 2 + khh) * SUB, SUB, mbf[st2]);
        bulk_g2s(dst + 65536u,  g_H_img + ((size_t)j * 2 + khh) * SUB, SUB, mbf[st2]);
        bulk_g2s(dst + 81920u,  g_L_img + ((size_t)j * 2 + khh) * SUB, SUB, mbf[st2]);
    };

    if (tid == 0) {
        if (total_g > 0) issue(0);
        if (total_g > 1) issue(1);
    }

    // per-lane ldmatrix address components
    const int aR = lane & 15;
    const int aK = (lane >> 4) * 16;
    const int bN = (lane & 7) + ((lane >> 4) << 3);
    const int bK = ((lane >> 3) & 1) * 16;
    unsigned aoff[4], asw[4];
    #pragma unroll
    for (int mi = 0; mi < 4; mi++) {
        int lr = (warp_m * 64 + mi * 16 + aR) & 127;
        aoff[mi] = (unsigned)lr * 128u;
        asw[mi]  = ((unsigned)lr & 7u) << 4;
    }
    unsigned boff[4], bsw[4];
    #pragma unroll
    for (int p = 0; p < 4; p++) {
        int r = warp_n * 64 + p * 16 + bN;
        boff[p] = (unsigned)r * 128u;
        bsw[p]  = ((unsigned)r & 7u) << 4;
    }
    const unsigned atile = ((unsigned)(warp_m >> 1)) * 32768u;
    const int qr = lane >> 2;
    const int qc = (lane & 3) * 2;

    float acc[4][8][4];
    int pcur = 0, jcur = 0;

    for (int g = 0; g < total_g; ++g) {
        const int st = g & 1;   // stage parity == khalf parity
        const int kh = g & 1;

        if (kh == 0) {
            int u = bid + (g >> 1) * NCTA;
            int p = 0, rem = u;
            while (rem >= NTILE - 2 * p) { rem -= NTILE - 2 * p; p++; }
            pcur = p; jcur = 2 * p + rem;
            __syncthreads();     // prior unit's flush done
            {
                int gr = pcur * 256 + tid;
                s_sqr[tid] = g_sq[gr]; s_clsr[tid] = g_cls[gr];
                s_apr[tid] = 0u; s_anr[tid] = 0x7f800000u;
                if (tid < 128) {
                    int gc = jcur * 128 + tid;
                    s_sqc[tid] = g_sq[gc]; s_clsc[tid] = g_cls[gc];
                    s_apc[tid] = 0u; s_anc[tid] = 0x7f800000u;
                }
            }
            __syncthreads();     // stats + reduction arrays ready
            #pragma unroll
            for (int mi = 0; mi < 4; mi++)
                #pragma unroll
                for (int ni = 0; ni < 8; ni++)
                    #pragma unroll
                    for (int x = 0; x < 4; x++) acc[mi][ni][x] = 0.0f;
        }

        mbar_wait(mbf[st], phf[st]); phf[st] ^= 1;

        const unsigned S = sbase + (unsigned)st * STAGE;
        const unsigned AH = S + atile, AL = AH + 16384u;
        const unsigned BH = S + 65536u, BL = S + 81920u;

        #pragma unroll
        for (int ks = 0; ks < 4; ++ks) {
            const unsigned kbA = (unsigned)(ks * 32 + aK);
            const unsigned kbB = (unsigned)(ks * 32 + bK);
            unsigned bh[4][4], bl[4][4];
            #pragma unroll
            for (int p = 0; p < 4; p++) {
                ldsm4(bh[p], BH + boff[p] + (kbB ^ bsw[p]));
                ldsm4(bl[p], BL + boff[p] + (kbB ^ bsw[p]));
            }
            #pragma unroll
            for (int mi = 0; mi < 4; mi++) {
                unsigned ah[4], al[4];
                ldsm4(ah, AH + aoff[mi] + (kbA ^ asw[mi]));
                ldsm4(al, AL + aoff[mi] + (kbA ^ asw[mi]));
                #pragma unroll
                for (int ni = 0; ni < 8; ni++) {
                    const int p = ni >> 1, s2 = (ni & 1) * 2;
                    mma16816(acc[mi][ni], ah, bh[p][s2], bh[p][s2 + 1]); // H.H
                    mma16816(acc[mi][ni], ah, bl[p][s2], bl[p][s2 + 1]); // H.L
                    mma16816(acc[mi][ni], al, bh[p][s2], bh[p][s2 + 1]); // L.H
                }
            }
        }
        if (lane == 0) mbar_arrive(mbe[st]);

        if (tid == 0 && g + 2 < total_g) {
            mbar_wait(mbe[st], phe[st]); phe[st] ^= 1;
            issue(g + 2);
        }

        if (kh == 1) {
            // ---- dual-sided epilogue into smem reduction arrays ----
            const int cb = warp_n * 64;
            float cmx[8][2], cmn[8][2];
            #pragma unroll
            for (int ni = 0; ni < 8; ni++) {
                cmx[ni][0] = cmx[ni][1] = -CUDART_INF_F;
                cmn[ni][0] = cmn[ni][1] =  CUDART_INF_F;
            }
            #pragma unroll
            for (int mi = 0; mi < 4; mi++) {
                const int rl = warp_m * 64 + mi * 16 + qr;
                const int rh = rl + 8;
                const float sql = s_sqr[rl], sqh = s_sqr[rh];
                const int crl = s_clsr[rl], crh = s_clsr[rh];
                float apl = -CUDART_INF_F, anl = CUDART_INF_F;
                float aph = -CUDART_INF_F, anh = CUDART_INF_F;
                #pragma unroll
                for (int ni = 0; ni < 8; ni++) {
                    const int c0 = cb + ni * 8 + qc, c1 = c0 + 1;
                    const float sc0 = s_sqc[c0], sc1 = s_sqc[c1];
                    const int k0 = s_clsc[c0], k1 = s_clsc[c1];
                    const float d00 = acc[mi][ni][0], d01 = acc[mi][ni][1];
                    const float d10 = acc[mi][ni][2], d11 = acc[mi][ni][3];
                    const bool m0l = (k0 == crl), m1l = (k1 == crl);
                    const bool m0h = (k0 == crh), m1h = (k1 == crh);
                    const float r00 = fmaf(-2.0f, d00, sc0), r01 = fmaf(-2.0f, d01, sc1);
                    const float r10 = fmaf(-2.0f, d10, sc0), r11 = fmaf(-2.0f, d11, sc1);
                    apl = fmaxf(apl, m0l ? r00 : -CUDART_INF_F);
                    apl = fmaxf(apl, m1l ? r01 : -CUDART_INF_F);
                    anl = fminf(anl, m0l ? CUDART_INF_F : r00);
                    anl = fminf(anl, m1l ? CUDART_INF_F : r01);
                    aph = fmaxf(aph, m0h ? r10 : -CUDART_INF_F);
                    aph = fmaxf(aph, m1h ? r11 : -CUDART_INF_F);
                    anh = fminf(anh, m0h ? CUDART_INF_F : r10);
                    anh = fminf(anh, m1h ? CUDART_INF_F : r11);
                    const float q00 = fmaf(-2.0f, d00, sql), q01 = fmaf(-2.0f, d01, sql);
                    const float q10 = fmaf(-2.0f, d10, sqh), q11 = fmaf(-2.0f, d11, sqh);
                    cmx[ni][0] = fmaxf(cmx[ni][0], m0l ? q00 : -CUDART_INF_F);
                    cmx[ni][0] = fmaxf(cmx[ni][0], m0h ? q10 : -CUDART_INF_F);
                    cmx[ni][1] = fmaxf(cmx[ni][1], m1l ? q01 : -CUDART_INF_F);
                    cmx[ni][1] = fmaxf(cmx[ni][1], m1h ? q11 : -CUDART_INF_F);
                    cmn[ni][0] = fminf(cmn[ni][0], m0l ? CUDART_INF_F : q00);
                    cmn[ni][0] = fminf(cmn[ni][0], m0h ? CUDART_INF_F : q10);
                    cmn[ni][1] = fminf(cmn[ni][1], m1l ? CUDART_INF_F : q01);
                    cmn[ni][1] = fminf(cmn[ni][1], m1h ? CUDART_INF_F : q11);
                }
                #pragma unroll
                for (int m = 1; m < 4; m <<= 1) {
                    apl = fmaxf(apl, __shfl_xor_sync(0xffffffffu, apl, m));
                    anl = fminf(anl, __shfl_xor_sync(0xffffffffu, anl, m));
                    aph = fmaxf(aph, __shfl_xor_sync(0xffffffffu, aph, m));
                    anh = fminf(anh, __shfl_xor_sync(0xffffffffu, anh, m));
                }
                if ((lane & 3) == 0) {
                    atomicMax(&s_apr[rl], __float_as_uint(fmaxf(sql + apl, 1e-12f)));
                    atomicMin(&s_anr[rl], __float_as_uint(fmaxf(sql + anl, 1e-12f)));
                    atomicMax(&s_apr[rh], __float_as_uint(fmaxf(sqh + aph, 1e-12f)));
                    atomicMin(&s_anr[rh], __float_as_uint(fmaxf(sqh + anh, 1e-12f)));
                }
            }
            #pragma unroll
            for (int ni = 0; ni < 8; ni++)
                #pragma unroll
                for (int j2 = 0; j2 < 2; j2++)
                    #pragma unroll
                    for (int m = 4; m < 32; m <<= 1) {
                        cmx[ni][j2] = fmaxf(cmx[ni][j2], __shfl_xor_sync(0xffffffffu, cmx[ni][j2], m));
                        cmn[ni][j2] = fminf(cmn[ni][j2], __shfl_xor_sync(0xffffffffu, cmn[ni][j2], m));
                    }
            if (qr == 0) {   // lanes 0..3
                #pragma unroll
                for (int ni = 0; ni < 8; ni++)
                    #pragma unroll
                    for (int j2 = 0; j2 < 2; j2++) {
                        const int c = cb + ni * 8 + (lane & 3) * 2 + j2;
                        const float sc = s_sqc[c];
                        atomicMax(&s_apc[c], __float_as_uint(fmaxf(cmx[ni][j2] + sc, 1e-12f)));
                        atomicMin(&s_anc[c], __float_as_uint(fmaxf(cmn[ni][j2] + sc, 1e-12f)));
                    }
            }
            __syncthreads();   // all smem reductions done
            {
                const int gr = pcur * 256 + tid;
                atomicMax(&g_ap[gr], s_apr[tid]);
                atomicMin(&g_an[gr], s_anr[tid]);
                if (tid < 128) {
                    const int gc = jcur * 128 + tid;
                    atomicMax(&g_ap[gc], s_apc[tid]);
                    atomicMin(&g_an[gc], s_anc[tid]);
                }
            }
        }
    }
}

// ---------------------------------------------------------------------------
// Kernel 3: per-row confusion + partial sums. 32 blocks x 256.
// ---------------------------------------------------------------------------
__global__ void confuse_kernel(const float* __restrict__ pred) {
    __shared__ float s_s[8], s_c[8];
    int i = blockIdx.x * 256 + threadIdx.x;

    const float* pr = pred + (size_t)i * NCLS;
    float l[NCLS];
    float mx = -CUDART_INF_F;
    #pragma unroll
    for (int c = 0; c < NCLS; c++) { l[c] = pr[c]; mx = fmaxf(mx, l[c]); }
    float s = 0.0f;
    #pragma unroll
    for (int c = 0; c < NCLS; c++) { l[c] = __expf(l[c] - mx); s += l[c]; }
    float inv = 1.0f / s;
    float v1 = -1.0f, v2 = -1.0f;
    int i1 = 0;
    #pragma unroll
    for (int c = 0; c < NCLS; c++) {
        float p = l[c] * inv;
        if (p > v1) { v2 = v1; v1 = p; i1 = c; }
        else if (p > v2) { v2 = p; }
    }
    bool confuse = ((v1 - v2) <= GAPV) || (i1 != g_cls[i]);

    float ap = sqrtf(__uint_as_float(g_ap[i]));
    float an = sqrtf(__uint_as_float(g_an[i]));
    float per = fmaxf(ap - an, 0.0f);
    float sum = confuse ? per : 0.0f;
    float cnt = confuse ? 1.0f : 0.0f;

    #pragma unroll
    for (int m = 16; m > 0; m >>= 1) {
        sum += __shfl_xor_sync(0xffffffffu, sum, m);
        cnt += __shfl_xor_sync(0xffffffffu, cnt, m);
    }
    int wid = threadIdx.x >> 5, lane = threadIdx.x & 31;
    if (lane == 0) { s_s[wid] = sum; s_c[wid] = cnt; }
    __syncthreads();
    if (threadIdx.x == 0) {
        float ts = 0.0f, tc = 0.0f;
        #pragma unroll
        for (int w2 = 0; w2 < 8; w2++) { ts += s_s[w2]; tc += s_c[w2]; }
        g_part[blockIdx.x * 2]     = ts;
        g_part[blockIdx.x * 2 + 1] = tc;
    }
}

__global__ void final_kernel(float* __restrict__ out) {
    float s = 0.0f, c = 0.0f;
    #pragma unroll
    for (int b = 0; b < 32; b++) { s += g_part[b * 2]; c += g_part[b * 2 + 1]; }
    out[0] = (c > 0.0f) ? (s / c) : 0.0f;
}

// ---------------------------------------------------------------------------
extern "C" void kernel_launch(void* const* d_in, const int* in_sizes, int n_in,
                              void* d_out, int out_size) {
    const float* X    = (const float*)d_in[0];
    const float* pred = (const float*)d_in[1];
    const int*   tgt  = (const int*)d_in[2];
    float* out = (float*)d_out;

    static int smem_set = 0;
    const int SMEM_DYN = NSTG * STAGE;   // 196608
    if (!smem_set) {
        cudaFuncSetAttribute(gram_kernel,
                             cudaFuncAttributeMaxDynamicSharedMemorySize, SMEM_DYN);
        smem_set = 1;
    }

    classes_kernel<<<8, 1024>>>(tgt);
    convert_kernel<<<NROWS / 8, 256>>>(X);
    probe_kernel<<<1, 32>>>();          // keeps ncu capture slot on gram_kernel
    gram_kernel<<<NCTA, 256, SMEM_DYN>>>();
    confuse_kernel<<<32, 256>>>(pred);
    final_kernel<<<1, 1>>>(out);
}